// round 16
// baseline (speedup 1.0000x reference)
#include <cuda_runtime.h>
#include <math.h>

#define BB 4
#define SS 2048
#define DD 512
#define HH 8
#define DVV 64

// Scratch (device globals: allocation-free per harness rules)
__device__ uint4 g_qh[BB*HH*16384];    // Q fp16 a-frags (pre-scaled by 0.125*log2e)
__device__ uint4 g_kh[BB*HH*16384];    // K fp16 b-frag pairs: [bh][t32][kp2][key8_8][lane32]
__device__ uint4 g_vh[BB*HH*16384];    // V fp16 b-frag pairs: [bh][t32][jp2][nt8][lane32]
__device__ uint4 g_hh[BB*128*32*32];   // heads fp16 a-frags: [b][m16_128][ks32][lane32]
__device__ uint4 g_xah[BB*32*128*32];  // x fp16 a-frags: [b][kstep32][m16_128][lane32]
__device__ uint4 g_wbh[4*16*64*32];    // weights fp16 b-frag pairs: [w][k32_16][n8_64][lane32]
__device__ float g_mb[BB*SS];          // (1-mask)*(-100)  (additive log2-domain mask term)

#define SCALE2 0.1803368801111244f   /* 0.125 * log2(e) */
#define MASKNEG (-100.0f)            /* masked log2-score; fp16 ex2 -> exactly 0 */
#define ONE2H  0x3C003C00u           /* fp16x2 {1.0, 1.0} */

// pack {lo, hi} floats -> fp16x2 register
__device__ __forceinline__ unsigned ph(float lo, float hi) {
    unsigned r;
    asm("cvt.rn.f16x2.f32 %0, %1, %2;" : "=r"(r) : "f"(hi), "f"(lo));
    return r;
}
// packed fp16x2 exp2
__device__ __forceinline__ unsigned h2ex2(unsigned x) {
    unsigned y;
    asm("ex2.approx.f16x2 %0, %1;" : "=r"(y) : "r"(x));
    return y;
}
__device__ __forceinline__ void mma16h(float* d, const unsigned* a, unsigned b0, unsigned b1) {
    asm volatile(
        "mma.sync.aligned.m16n8k16.row.col.f32.f16.f16.f32 "
        "{%0,%1,%2,%3},{%4,%5,%6,%7},{%8,%9},{%0,%1,%2,%3};\n"
        : "+f"(d[0]), "+f"(d[1]), "+f"(d[2]), "+f"(d[3])
        : "r"(a[0]), "r"(a[1]), "r"(a[2]), "r"(a[3]), "r"(b0), "r"(b1));
}
__device__ __forceinline__ void cpa16(const void* s, const void* g) {
    unsigned sa = (unsigned)__cvta_generic_to_shared(s);
    asm volatile("cp.async.cg.shared.global [%0], [%1], 16;\n" :: "r"(sa), "l"(g));
}
__device__ __forceinline__ void cp_commit() {
    asm volatile("cp.async.commit_group;\n");
}
__device__ __forceinline__ void cp_wait0() {
    asm volatile("cp.async.wait_group 0;\n");
}

// ---------------------------------------------------------------------------
// Kernel 0: fused pre-formatting.
//   blocks [0,1024):     x -> g_xah (fp16 a-fragment uint4) via smem transpose
//   blocks [1024,1536):  weights -> g_wbh (fp16 b-fragment-pair uint4)
//   blocks [1536,1544):  mask -> g_mb additive term
// ---------------------------------------------------------------------------
__global__ __launch_bounds__(256) void round_xw(
    const float* __restrict__ x, const float* __restrict__ mask,
    const float* __restrict__ Wq, const float* __restrict__ Wk,
    const float* __restrict__ Wv, const float* __restrict__ W0)
{
    int tid = threadIdx.x;
    if (blockIdx.x < 1024) {
        __shared__ float As[32][136];
        int bz = blockIdx.x;
        int m16b = bz & 15, k32i = (bz >> 4) & 15, b = bz >> 8;
        int k0 = k32i * 32, m0 = m16b * 128;
        const float* xb = x + (size_t)b * DD * SS;

        for (int i = tid; i < 1024; i += 256) {
            int kk = i >> 5, m4 = i & 31;
            *(float4*)&As[kk][m4 * 4] =
                *(const float4*)&xb[(size_t)(k0 + kk) * SS + m0 + m4 * 4];
        }
        __syncthreads();

        int m16_0 = m0 >> 4;
        for (int i = tid; i < 512; i += 256) {
            int ks = i >> 8, rem = i & 255;
            int m16l = rem >> 5, lane = rem & 31, gid = lane >> 2, tig = lane & 3;
            int kb = ks * 16, m = m16l * 16 + gid;
            uint4 v;
            v.x = ph(As[kb + 2*tig][m],     As[kb + 2*tig + 1][m]);
            v.y = ph(As[kb + 2*tig][m + 8], As[kb + 2*tig + 1][m + 8]);
            v.z = ph(As[kb + 8 + 2*tig][m],     As[kb + 9 + 2*tig][m]);
            v.w = ph(As[kb + 8 + 2*tig][m + 8], As[kb + 9 + 2*tig][m + 8]);
            g_xah[(((size_t)b * 32 + k32i * 2 + ks) * 128 + m16_0 + m16l) * 32 + lane] = v;
        }
    } else if (blockIdx.x < 1536) {
        int o = (blockIdx.x - 1024) * 256 + tid;   // one uint4 per thread
        int lane = o & 31, n8 = (o >> 5) & 63, k32 = (o >> 11) & 15, w = o >> 15;
        int gid = lane >> 2, tig = lane & 3;
        const float* W = (w == 0) ? Wq : (w == 1) ? Wk : (w == 2) ? Wv : W0;
        const float* r = W + (n8 * 8 + gid) * DD + k32 * 32;
        uint4 v;
        v.x = ph(r[2*tig],      r[2*tig + 1]);
        v.y = ph(r[2*tig + 8],  r[2*tig + 9]);
        v.z = ph(r[16 + 2*tig], r[16 + 2*tig + 1]);
        v.w = ph(r[24 + 2*tig], r[24 + 2*tig + 1]);
        g_wbh[o] = v;
    } else {
        int i = (blockIdx.x - 1536) * 256 + tid;   // float4 index, 2048 total
        float4 m4 = ((const float4*)mask)[i];
        float4 v;
        v.x = (1.f - m4.x) * MASKNEG;
        v.y = (1.f - m4.y) * MASKNEG;
        v.z = (1.f - m4.z) * MASKNEG;
        v.w = (1.f - m4.w) * MASKNEG;
        ((float4*)g_mb)[i] = v;
    }
}

// ---------------------------------------------------------------------------
// Kernel 1: QKV projection, full fp16 (m16n8k16). Per k32: 8+4 LDS.128,
// 32 HMMA. cp.async double-buffered, 1 sync/K-step. Epilogues emit fp16
// MMA fragments straight from the accumulators; Q pre-scaled by SCALE2.
// ---------------------------------------------------------------------------
#define QKV_SMEM 32768   // A: 2*512 uint4 (16KB) + B: 2*512 uint4 (16KB)

__global__ __launch_bounds__(256, 2) void qkv_mma(
    const float* __restrict__ bq, const float* __restrict__ bk,
    const float* __restrict__ bv)
{
    extern __shared__ float dyn[];
    uint4* A4 = (uint4*)dyn;          // 2 * 512
    uint4* B4 = A4 + 1024;            // 2 * 512

    int b = blockIdx.z / 3, w = blockIdx.z % 3;
    const float* bias = (w == 0) ? bq : (w == 1) ? bk : bv;

    int m0 = blockIdx.x * 128, n0 = blockIdx.y * 128;
    int m16_0 = m0 >> 4, n8_0 = n0 >> 3;
    int tid = threadIdx.x, lane = tid & 31, warp = tid >> 5;
    int wm = warp & 1, wn = warp >> 1;
    int gid = lane >> 2, tig = lane & 3;

    const uint4* xa = g_xah + (size_t)b * 32 * 128 * 32;
    const uint4* wb = g_wbh + (size_t)w * 16 * 64 * 32;

    auto stage = [&](int buf, int it) {
        uint4* Ab = A4 + buf * 512;
        uint4* Bb = B4 + buf * 512;
#pragma unroll
        for (int i = tid; i < 512; i += 256) {
            int ks = i >> 8, rem = i & 255;
            int m16l = rem >> 5, ln = rem & 31;
            cpa16(&Ab[i], &xa[((size_t)(it * 2 + ks) * 128 + m16_0 + m16l) * 32 + ln]);
        }
#pragma unroll
        for (int i = tid; i < 512; i += 256) {
            int n8l = i >> 5, ln = i & 31;
            cpa16(&Bb[i], &wb[((size_t)it * 64 + n8_0 + n8l) * 32 + ln]);
        }
        cp_commit();
    };

    float acc[4][4][4];
#pragma unroll
    for (int mt = 0; mt < 4; mt++)
#pragma unroll
        for (int nt = 0; nt < 4; nt++)
#pragma unroll
            for (int j = 0; j < 4; j++) acc[mt][nt][j] = 0.f;

    stage(0, 0);
    for (int it = 0; it < 16; it++) {
        cp_wait0();
        __syncthreads();
        if (it < 15) stage((it + 1) & 1, it + 1);
        const uint4* Ab = A4 + (it & 1) * 512;
        const uint4* Bb = B4 + (it & 1) * 512;

        uint4 bf[4];
#pragma unroll
        for (int nt = 0; nt < 4; nt++)
            bf[nt] = Bb[(wn * 4 + nt) * 32 + lane];
#pragma unroll
        for (int kp = 0; kp < 2; kp++) {
            uint4 af[4];
#pragma unroll
            for (int mt = 0; mt < 4; mt++)
                af[mt] = Ab[(kp * 8 + wm * 4 + mt) * 32 + lane];
#pragma unroll
            for (int mt = 0; mt < 4; mt++)
#pragma unroll
                for (int nt = 0; nt < 4; nt++)
                    mma16h(acc[mt][nt], (const unsigned*)&af[mt],
                           kp ? bf[nt].z : bf[nt].x, kp ? bf[nt].w : bf[nt].y);
        }
    }

    int h = blockIdx.y * 2 + (wn >> 1);
    size_t bh = (size_t)b * HH + h;
    int kp = wn & 1;

    if (w == 0) {
        // Q -> fp16 a-fragments, pre-scaled by SCALE2 (softmax scale folded in).
#pragma unroll
        for (int mt = 0; mt < 4; mt++) {
            int m16 = (m0 + wm * 64 + mt * 16) >> 4;
#pragma unroll
            for (int sp = 0; sp < 2; sp++) {
                int ntA = 2 * sp, ntB = ntA + 1;
                int nA = n0 + wn * 32 + ntA * 8 + tig * 2;
                int nB = nA + 8;
                float bA0 = bias[nA], bA1 = bias[nA + 1];
                float bB0 = bias[nB], bB1 = bias[nB + 1];
                unsigned a0 = ph((acc[mt][ntA][0] + bA0) * SCALE2, (acc[mt][ntA][1] + bA1) * SCALE2);
                unsigned a1 = ph((acc[mt][ntA][2] + bA0) * SCALE2, (acc[mt][ntA][3] + bA1) * SCALE2);
                unsigned a2 = ph((acc[mt][ntB][0] + bB0) * SCALE2, (acc[mt][ntB][1] + bB1) * SCALE2);
                unsigned a3 = ph((acc[mt][ntB][2] + bB0) * SCALE2, (acc[mt][ntB][3] + bB1) * SCALE2);
                int kstep = 2 * kp + sp;
                g_qh[((bh * 128 + m16) * 4 + kstep) * 32 + lane] =
                    make_uint4(a0, a1, a2, a3);
            }
        }
    } else if (w == 1) {
        // K -> fp16 b-fragment pairs, straight from accumulators.
#pragma unroll
        for (int mt = 0; mt < 4; mt++) {
            int r = m0 + wm * 64 + mt * 16 + gid;
            int t = r >> 6, key8 = (r >> 3) & 7;
            unsigned s_b0r0, s_b1r0, s_b0r8, s_b1r8;
#pragma unroll
            for (int sp = 0; sp < 2; sp++) {
                int ntA = 2 * sp, ntB = ntA + 1;
                int nA = n0 + wn * 32 + ntA * 8 + tig * 2;
                int nB = nA + 8;
                float bA0 = bias[nA], bA1 = bias[nA + 1];
                float bB0 = bias[nB], bB1 = bias[nB + 1];
                unsigned b0r0 = ph(acc[mt][ntA][0] + bA0, acc[mt][ntA][1] + bA1);
                unsigned b1r0 = ph(acc[mt][ntB][0] + bB0, acc[mt][ntB][1] + bB1);
                unsigned b0r8 = ph(acc[mt][ntA][2] + bA0, acc[mt][ntA][3] + bA1);
                unsigned b1r8 = ph(acc[mt][ntB][2] + bB0, acc[mt][ntB][3] + bB1);
                if (sp == 0) { s_b0r0 = b0r0; s_b1r0 = b1r0; s_b0r8 = b0r8; s_b1r8 = b1r8; }
                else {
                    uint4* p = g_kh + bh * 16384;
                    p[(((t * 2 + kp) * 8 + key8) * 8 + gid) * 4 + tig] =
                        make_uint4(s_b0r0, s_b1r0, b0r0, b1r0);
                    p[(((t * 2 + kp) * 8 + key8 + 1) * 8 + gid) * 4 + tig] =
                        make_uint4(s_b0r8, s_b1r8, b0r8, b1r8);
                }
            }
        }
    } else {
        // V -> fp16 b-fragment pairs via per-warp smem transpose (pad 12).
        float* sv = dyn + warp * 200;   // reuses A buffer 0 (mainloop ended on buf 1)
        int tt = blockIdx.x * 2 + wm;
        uint2 vbuf[4];
#pragma unroll
        for (int mt = 0; mt < 4; mt++) {
#pragma unroll
            for (int nt = 0; nt < 4; nt++) {
                int nb = n0 + wn * 32 + nt * 8;
                int nf = nb + tig * 2;
                float c0 = acc[mt][nt][0] + bias[nf];
                float c1 = acc[mt][nt][1] + bias[nf + 1];
                float c2 = acc[mt][nt][2] + bias[nf];
                float c3 = acc[mt][nt][3] + bias[nf + 1];
                sv[gid * 12 + tig * 2]           = c0;
                sv[gid * 12 + tig * 2 + 1]       = c1;
                sv[(gid + 8) * 12 + tig * 2]     = c2;
                sv[(gid + 8) * 12 + tig * 2 + 1] = c3;
                __syncwarp();
                float a0 = sv[(2 * tig) * 12 + gid];
                float a1 = sv[(2 * tig + 1) * 12 + gid];
                float a2 = sv[(2 * tig + 8) * 12 + gid];
                float a3 = sv[(2 * tig + 9) * 12 + gid];
                __syncwarp();
                uint2 val = make_uint2(ph(a0, a1), ph(a2, a3));
                if ((mt & 1) == 0) vbuf[nt] = val;
                else {
                    int jp = mt >> 1;
                    int hv = nb >> 6;
                    int ev3 = (nb & 63) >> 3;
                    size_t bhv = (size_t)b * HH + hv;
                    g_vh[bhv * 16384 + (size_t)tt * 512 + ((jp * 8 + ev3) * 8 + gid) * 4 + tig] =
                        make_uint4(vbuf[nt].x, vbuf[nt].y, val.x, val.y);
                }
            }
        }
    }
}

// ---------------------------------------------------------------------------
// Kernel 2: flash attention, full fp16 tensor path. Softmax: mask-FMA in f32,
// pack to fp16x2, then ONE packed ex2.approx.f16x2 per pair (MUFU halved);
// results ARE the PV a-fragments. Row sums via ones-column MMA.
// ---------------------------------------------------------------------------
#define KU4PT 512                            // uint4 per K tile (8 KB)
#define VU4PT 512                            // uint4 per V tile (8 KB)
#define ATTN_SMEM ((2*KU4PT + 2*VU4PT) * 16) // 32768 B

extern __shared__ float smx[];

__global__ __launch_bounds__(256, 2) void attn_mma(const float* __restrict__ mask)
{
    uint4* Ksm = (uint4*)smx;
    uint4* Vsm = Ksm + 2 * KU4PT;

    int bh = blockIdx.y, b = bh >> 3, h = bh & 7;
    int m0 = blockIdx.x * 128;
    int tid = threadIdx.x, lane = tid & 31, w = tid >> 5;
    int gid = lane >> 2, tig = lane & 3;

    const uint4*  kpf   = g_kh + (size_t)bh * 16384;
    const uint4*  vpf   = g_vh + (size_t)bh * 16384;
    const float*  mrow  = mask + (size_t)b * SS;
    const float*  mbrow = g_mb + (size_t)b * SS;

    auto stageKV = [&](int buf, int t) {
        uint4* Kb = Ksm + buf * KU4PT;
        uint4* Vb = Vsm + buf * VU4PT;
        const uint4* ks = kpf + t * KU4PT;
        const uint4* vs = vpf + t * VU4PT;
#pragma unroll
        for (int i = tid; i < 512; i += 256) cpa16(&Kb[i], &ks[i]);
#pragma unroll
        for (int i = tid; i < 512; i += 256) cpa16(&Vb[i], &vs[i]);
        cp_commit();
    };

    stageKV(0, 0);

    int r0 = w * 16 + gid;
    int m16 = (m0 >> 4) + w;

    // Q fp16 a-fragments -> registers (once; 4 LDG.128)
    uint4 qf4[4];
#pragma unroll
    for (int s = 0; s < 4; s++)
        qf4[s] = g_qh[(((size_t)bh * 128 + m16) * 4 + s) * 32 + lane];

    float lacc[4] = {0.f, 0.f, 0.f, 0.f};
    float oacc[8][4];
#pragma unroll
    for (int nt = 0; nt < 8; nt++)
#pragma unroll
        for (int j = 0; j < 4; j++) oacc[nt][j] = 0.f;

    for (int t = 0; t < 32; t++) {
        int t0 = t * 64;
        cp_wait0();
        __syncthreads();
        if (t < 31) stageKV((t + 1) & 1, t + 1);

        const uint4* Kb = Ksm + (t & 1) * KU4PT;
        const uint4* Vb = Vsm + (t & 1) * VU4PT;

        // ---- S = Qs @ K^T (fp16 m16n8k16; S already in log2 units) ----
        float sacc[8][4];
#pragma unroll
        for (int nt = 0; nt < 8; nt++)
#pragma unroll
            for (int j = 0; j < 4; j++) sacc[nt][j] = 0.f;

#pragma unroll
        for (int kp = 0; kp < 2; kp++) {
            const unsigned* afe = (const unsigned*)&qf4[2 * kp];
            const unsigned* afo = (const unsigned*)&qf4[2 * kp + 1];
#pragma unroll
            for (int nt = 0; nt < 8; nt++) {
                uint4 k4 = Kb[((kp * 8 + nt) * 8 + gid) * 4 + tig];
                mma16h(sacc[nt], afe, k4.x, k4.y);
                mma16h(sacc[nt], afo, k4.z, k4.w);
            }
        }

        // ---- mask-FMA (f32) -> pack fp16x2 -> packed ex2 (P = a-fragments) ----
        unsigned pf[8][2];
#pragma unroll
        for (int nt = 0; nt < 8; nt++) {
            float2 mv = *(const float2*)&mrow[t0 + nt * 8 + tig * 2];
            float2 ad = *(const float2*)&mbrow[t0 + nt * 8 + tig * 2];
            float f0 = sacc[nt][0] * mv.x + ad.x;
            float f1 = sacc[nt][1] * mv.y + ad.y;
            float f2 = sacc[nt][2] * mv.x + ad.x;
            float f3 = sacc[nt][3] * mv.y + ad.y;
            pf[nt][0] = h2ex2(ph(f0, f1));   // rows gid
            pf[nt][1] = h2ex2(ph(f2, f3));   // rows gid+8
        }

        // ---- O += P @ V (fp16); row sums via ones-MMA ----
#pragma unroll
        for (int jp = 0; jp < 2; jp++) {
            unsigned afe[4] = {pf[4*jp][0],   pf[4*jp][1],   pf[4*jp+1][0], pf[4*jp+1][1]};
            unsigned afo[4] = {pf[4*jp+2][0], pf[4*jp+2][1], pf[4*jp+3][0], pf[4*jp+3][1]};
            mma16h(lacc, afe, ONE2H, ONE2H);
            mma16h(lacc, afo, ONE2H, ONE2H);
#pragma unroll
            for (int nt = 0; nt < 8; nt++) {
                uint4 v4 = Vb[((jp * 8 + nt) * 8 + gid) * 4 + tig];
                mma16h(oacc[nt], afe, v4.x, v4.y);
                mma16h(oacc[nt], afo, v4.z, v4.w);
            }
        }
    }

    // lacc[0]/lacc[2] are full row sums (ones-column trick)
    int s0r = m0 + r0, s1r = s0r + 8;
    float q0 = mrow[s0r] / lacc[0];
    float q1 = mrow[s1r] / lacc[2];
#pragma unroll
    for (int ks = 0; ks < 4; ks++) {
        uint4 hv;
        hv.x = ph(oacc[2*ks][0] * q0,   oacc[2*ks][1] * q0);
        hv.y = ph(oacc[2*ks][2] * q1,   oacc[2*ks][3] * q1);
        hv.z = ph(oacc[2*ks+1][0] * q0, oacc[2*ks+1][1] * q0);
        hv.w = ph(oacc[2*ks+1][2] * q1, oacc[2*ks+1][3] * q1);
        g_hh[(((size_t)b * 128 + m16) * 32 + h * 4 + ks) * 32 + lane] = hv;
    }
}

// ---------------------------------------------------------------------------
// Kernel 3: output projection, full fp16 (same pipeline shape as qkv).
// ---------------------------------------------------------------------------
#define PROJ_SMEM 32768

__global__ __launch_bounds__(256, 2) void proj_mma(
    const float* __restrict__ b0, float* __restrict__ out)
{
    extern __shared__ float dyn[];
    uint4* A4 = (uint4*)dyn;          // 2 * 512
    uint4* B4 = A4 + 1024;            // 2 * 512

    int b = blockIdx.z;
    int m0 = blockIdx.x * 128, n0 = blockIdx.y * 128;
    int m16_0 = m0 >> 4, n8_0 = n0 >> 3;
    int tid = threadIdx.x, lane = tid & 31, warp = tid >> 5;
    int wm = warp & 1, wn = warp >> 1;
    int gid = lane >> 2, tig = lane & 3;

    const uint4* ha = g_hh + (size_t)b * 128 * 32 * 32;
    const uint4* wb = g_wbh + (size_t)3 * 16 * 64 * 32;

    auto stage = [&](int buf, int it) {
        uint4* Ab = A4 + buf * 512;
        uint4* Bb = B4 + buf * 512;
#pragma unroll
        for (int i = tid; i < 512; i += 256) {
            int ks = i >> 8, rem = i & 255;
            int m16l = rem >> 5, ln = rem & 31;
            cpa16(&Ab[i], &ha[((size_t)(m16_0 + m16l) * 32 + it * 2 + ks) * 32 + ln]);
        }
#pragma unroll
        for (int i = tid; i < 512; i += 256) {
            int n8l = i >> 5, ln = i & 31;
            cpa16(&Bb[i], &wb[((size_t)it * 64 + n8_0 + n8l) * 32 + ln]);
        }
        cp_commit();
    };

    float acc[4][4][4];
#pragma unroll
    for (int mt = 0; mt < 4; mt++)
#pragma unroll
        for (int nt = 0; nt < 4; nt++)
#pragma unroll
            for (int j = 0; j < 4; j++) acc[mt][nt][j] = 0.f;

    stage(0, 0);
    for (int it = 0; it < 16; it++) {
        cp_wait0();
        __syncthreads();
        if (it < 15) stage((it + 1) & 1, it + 1);
        const uint4* Ab = A4 + (it & 1) * 512;
        const uint4* Bb = B4 + (it & 1) * 512;

        uint4 bf[4];
#pragma unroll
        for (int nt = 0; nt < 4; nt++)
            bf[nt] = Bb[(wn * 4 + nt) * 32 + lane];
#pragma unroll
        for (int kp = 0; kp < 2; kp++) {
            uint4 af[4];
#pragma unroll
            for (int mt = 0; mt < 4; mt++)
                af[mt] = Ab[(kp * 8 + wm * 4 + mt) * 32 + lane];
#pragma unroll
            for (int mt = 0; mt < 4; mt++)
#pragma unroll
                for (int nt = 0; nt < 4; nt++)
                    mma16h(acc[mt][nt], (const unsigned*)&af[mt],
                           kp ? bf[nt].z : bf[nt].x, kp ? bf[nt].w : bf[nt].y);
        }
    }

#pragma unroll
    for (int mt = 0; mt < 4; mt++)
#pragma unroll
        for (int nt = 0; nt < 4; nt++) {
            int n = n0 + wn * 32 + nt * 8 + tig * 2;
            int r = m0 + wm * 64 + mt * 16 + gid;
            float b0v = b0[n], b1v = b0[n + 1];
            size_t c0 = ((size_t)b * DD + n) * SS;
            size_t c1 = c0 + SS;
            out[c0 + r]     = acc[mt][nt][0] + b0v;
            out[c1 + r]     = acc[mt][nt][1] + b1v;
            out[c0 + r + 8] = acc[mt][nt][2] + b0v;
            out[c1 + r + 8] = acc[mt][nt][3] + b1v;
        }
}

// ---------------------------------------------------------------------------
extern "C" void kernel_launch(void* const* d_in, const int* in_sizes, int n_in,
                              void* d_out, int out_size)
{
    const float* x    = (const float*)d_in[0];
    const float* mask = (const float*)d_in[1];
    const float* Wq   = (const float*)d_in[2];
    const float* bq   = (const float*)d_in[3];
    const float* Wk   = (const float*)d_in[4];
    const float* bk   = (const float*)d_in[5];
    const float* Wv   = (const float*)d_in[6];
    const float* bv   = (const float*)d_in[7];
    const float* W0   = (const float*)d_in[8];
    const float* b0   = (const float*)d_in[9];
    float* out = (float*)d_out;

    cudaFuncSetAttribute(qkv_mma,
                         cudaFuncAttributeMaxDynamicSharedMemorySize, QKV_SMEM);
    cudaFuncSetAttribute(attn_mma,
                         cudaFuncAttributeMaxDynamicSharedMemorySize, ATTN_SMEM);
    cudaFuncSetAttribute(proj_mma,
                         cudaFuncAttributeMaxDynamicSharedMemorySize, PROJ_SMEM);

    round_xw<<<1544, 256>>>(x, mask, Wq, Wk, Wv, W0);
    qkv_mma<<<dim3(SS/128, DD/128, BB*3), 256, QKV_SMEM>>>(bq, bk, bv);
    attn_mma<<<dim3(SS/128, BB*HH), 256, ATTN_SMEM>>>(mask);
    proj_mma<<<dim3(SS/128, DD/128, BB), 256, PROJ_SMEM>>>(b0, out);
}

// round 17
// speedup vs baseline: 1.0332x; 1.0332x over previous
#include <cuda_runtime.h>
#include <math.h>

#define BB 4
#define SS 2048
#define DD 512
#define HH 8
#define DVV 64

// Scratch (device globals: allocation-free per harness rules)
__device__ uint4 g_qh[BB*HH*16384];    // Q fp16 a-frags (pre-scaled by 0.125*log2e)
__device__ uint4 g_kh[BB*HH*16384];    // K fp16 b-frag pairs: [bh][t32][kp2][key8_8][lane32]
__device__ uint4 g_vh[BB*HH*16384];    // V fp16 b-frag pairs: [bh][t32][jp2][nt8][lane32]
__device__ uint4 g_hh[BB*128*32*32];   // heads fp16 a-frags: [b][m16_128][ks32][lane32]
__device__ uint4 g_xah[BB*32*128*32];  // x fp16 a-frags: [b][kstep32][m16_128][lane32]
__device__ uint4 g_wbh[4*16*64*32];    // weights fp16 b-frag pairs: [w][k32_16][n8_64][lane32]

#define SCALE2 0.1803368801111244f   /* 0.125 * log2(e) */
#define NEG2F  (-1.442695e30f)       /* NEG_INF * log2(e) */
#define ONE2H  0x3C003C00u           /* fp16x2 {1.0, 1.0} */

__device__ __forceinline__ float ex2(float x) {
    float y;
    asm("ex2.approx.ftz.f32 %0, %1;" : "=f"(y) : "f"(x));
    return y;
}
// pack {lo, hi} floats -> fp16x2 register
__device__ __forceinline__ unsigned ph(float lo, float hi) {
    unsigned r;
    asm("cvt.rn.f16x2.f32 %0, %1, %2;" : "=r"(r) : "f"(hi), "f"(lo));
    return r;
}
__device__ __forceinline__ void mma16h(float* d, const unsigned* a, unsigned b0, unsigned b1) {
    asm volatile(
        "mma.sync.aligned.m16n8k16.row.col.f32.f16.f16.f32 "
        "{%0,%1,%2,%3},{%4,%5,%6,%7},{%8,%9},{%0,%1,%2,%3};\n"
        : "+f"(d[0]), "+f"(d[1]), "+f"(d[2]), "+f"(d[3])
        : "r"(a[0]), "r"(a[1]), "r"(a[2]), "r"(a[3]), "r"(b0), "r"(b1));
}
__device__ __forceinline__ void cpa16(const void* s, const void* g) {
    unsigned sa = (unsigned)__cvta_generic_to_shared(s);
    asm volatile("cp.async.cg.shared.global [%0], [%1], 16;\n" :: "r"(sa), "l"(g));
}
__device__ __forceinline__ void cp_commit() {
    asm volatile("cp.async.commit_group;\n");
}
__device__ __forceinline__ void cp_wait0() {
    asm volatile("cp.async.wait_group 0;\n");
}

// ---------------------------------------------------------------------------
// Kernel 0: fused pre-formatting.
//   blocks [0,1024):     x -> g_xah (fp16 a-fragment uint4) via smem transpose
//   blocks [1024,1536):  weights -> g_wbh (fp16 b-fragment-pair uint4)
// ---------------------------------------------------------------------------
__global__ __launch_bounds__(256) void round_xw(
    const float* __restrict__ x,
    const float* __restrict__ Wq, const float* __restrict__ Wk,
    const float* __restrict__ Wv, const float* __restrict__ W0)
{
    int tid = threadIdx.x;
    if (blockIdx.x < 1024) {
        __shared__ float As[32][136];
        int bz = blockIdx.x;
        int m16b = bz & 15, k32i = (bz >> 4) & 15, b = bz >> 8;
        int k0 = k32i * 32, m0 = m16b * 128;
        const float* xb = x + (size_t)b * DD * SS;

        for (int i = tid; i < 1024; i += 256) {
            int kk = i >> 5, m4 = i & 31;
            *(float4*)&As[kk][m4 * 4] =
                *(const float4*)&xb[(size_t)(k0 + kk) * SS + m0 + m4 * 4];
        }
        __syncthreads();

        int m16_0 = m0 >> 4;
        for (int i = tid; i < 512; i += 256) {
            int ks = i >> 8, rem = i & 255;
            int m16l = rem >> 5, lane = rem & 31, gid = lane >> 2, tig = lane & 3;
            int kb = ks * 16, m = m16l * 16 + gid;
            uint4 v;
            v.x = ph(As[kb + 2*tig][m],     As[kb + 2*tig + 1][m]);
            v.y = ph(As[kb + 2*tig][m + 8], As[kb + 2*tig + 1][m + 8]);
            v.z = ph(As[kb + 8 + 2*tig][m],     As[kb + 9 + 2*tig][m]);
            v.w = ph(As[kb + 8 + 2*tig][m + 8], As[kb + 9 + 2*tig][m + 8]);
            g_xah[(((size_t)b * 32 + k32i * 2 + ks) * 128 + m16_0 + m16l) * 32 + lane] = v;
        }
    } else {
        int o = (blockIdx.x - 1024) * 256 + tid;   // one uint4 per thread
        int lane = o & 31, n8 = (o >> 5) & 63, k32 = (o >> 11) & 15, w = o >> 15;
        int gid = lane >> 2, tig = lane & 3;
        const float* W = (w == 0) ? Wq : (w == 1) ? Wk : (w == 2) ? Wv : W0;
        const float* r = W + (n8 * 8 + gid) * DD + k32 * 32;
        uint4 v;
        v.x = ph(r[2*tig],      r[2*tig + 1]);
        v.y = ph(r[2*tig + 8],  r[2*tig + 9]);
        v.z = ph(r[16 + 2*tig], r[16 + 2*tig + 1]);
        v.w = ph(r[24 + 2*tig], r[24 + 2*tig + 1]);
        g_wbh[o] = v;
    }
}

// ---------------------------------------------------------------------------
// Kernel 1: QKV projection, full fp16 (m16n8k16). Per k32: 8+4 LDS.128,
// 32 HMMA. cp.async double-buffered, 1 sync/K-step. Epilogues emit fp16
// MMA fragments straight from the accumulators; Q pre-scaled by SCALE2.
// ---------------------------------------------------------------------------
#define QKV_SMEM 32768   // A: 2*512 uint4 (16KB) + B: 2*512 uint4 (16KB)

__global__ __launch_bounds__(256, 2) void qkv_mma(
    const float* __restrict__ bq, const float* __restrict__ bk,
    const float* __restrict__ bv)
{
    extern __shared__ float dyn[];
    uint4* A4 = (uint4*)dyn;          // 2 * 512
    uint4* B4 = A4 + 1024;            // 2 * 512

    int b = blockIdx.z / 3, w = blockIdx.z % 3;
    const float* bias = (w == 0) ? bq : (w == 1) ? bk : bv;

    int m0 = blockIdx.x * 128, n0 = blockIdx.y * 128;
    int m16_0 = m0 >> 4, n8_0 = n0 >> 3;
    int tid = threadIdx.x, lane = tid & 31, warp = tid >> 5;
    int wm = warp & 1, wn = warp >> 1;
    int gid = lane >> 2, tig = lane & 3;

    const uint4* xa = g_xah + (size_t)b * 32 * 128 * 32;
    const uint4* wb = g_wbh + (size_t)w * 16 * 64 * 32;

    auto stage = [&](int buf, int it) {
        uint4* Ab = A4 + buf * 512;
        uint4* Bb = B4 + buf * 512;
#pragma unroll
        for (int i = tid; i < 512; i += 256) {
            int ks = i >> 8, rem = i & 255;
            int m16l = rem >> 5, ln = rem & 31;
            cpa16(&Ab[i], &xa[((size_t)(it * 2 + ks) * 128 + m16_0 + m16l) * 32 + ln]);
        }
#pragma unroll
        for (int i = tid; i < 512; i += 256) {
            int n8l = i >> 5, ln = i & 31;
            cpa16(&Bb[i], &wb[((size_t)it * 64 + n8_0 + n8l) * 32 + ln]);
        }
        cp_commit();
    };

    float acc[4][4][4];
#pragma unroll
    for (int mt = 0; mt < 4; mt++)
#pragma unroll
        for (int nt = 0; nt < 4; nt++)
#pragma unroll
            for (int j = 0; j < 4; j++) acc[mt][nt][j] = 0.f;

    stage(0, 0);
    for (int it = 0; it < 16; it++) {
        cp_wait0();
        __syncthreads();
        if (it < 15) stage((it + 1) & 1, it + 1);
        const uint4* Ab = A4 + (it & 1) * 512;
        const uint4* Bb = B4 + (it & 1) * 512;

        uint4 bf[4];
#pragma unroll
        for (int nt = 0; nt < 4; nt++)
            bf[nt] = Bb[(wn * 4 + nt) * 32 + lane];
#pragma unroll
        for (int kp = 0; kp < 2; kp++) {
            uint4 af[4];
#pragma unroll
            for (int mt = 0; mt < 4; mt++)
                af[mt] = Ab[(kp * 8 + wm * 4 + mt) * 32 + lane];
#pragma unroll
            for (int mt = 0; mt < 4; mt++)
#pragma unroll
                for (int nt = 0; nt < 4; nt++)
                    mma16h(acc[mt][nt], (const unsigned*)&af[mt],
                           kp ? bf[nt].z : bf[nt].x, kp ? bf[nt].w : bf[nt].y);
        }
    }

    int h = blockIdx.y * 2 + (wn >> 1);
    size_t bh = (size_t)b * HH + h;
    int kp = wn & 1;

    if (w == 0) {
        // Q -> fp16 a-fragments, pre-scaled by SCALE2 (softmax scale folded in).
#pragma unroll
        for (int mt = 0; mt < 4; mt++) {
            int m16 = (m0 + wm * 64 + mt * 16) >> 4;
#pragma unroll
            for (int sp = 0; sp < 2; sp++) {
                int ntA = 2 * sp, ntB = ntA + 1;
                int nA = n0 + wn * 32 + ntA * 8 + tig * 2;
                int nB = nA + 8;
                float bA0 = bias[nA], bA1 = bias[nA + 1];
                float bB0 = bias[nB], bB1 = bias[nB + 1];
                unsigned a0 = ph((acc[mt][ntA][0] + bA0) * SCALE2, (acc[mt][ntA][1] + bA1) * SCALE2);
                unsigned a1 = ph((acc[mt][ntA][2] + bA0) * SCALE2, (acc[mt][ntA][3] + bA1) * SCALE2);
                unsigned a2 = ph((acc[mt][ntB][0] + bB0) * SCALE2, (acc[mt][ntB][1] + bB1) * SCALE2);
                unsigned a3 = ph((acc[mt][ntB][2] + bB0) * SCALE2, (acc[mt][ntB][3] + bB1) * SCALE2);
                int kstep = 2 * kp + sp;
                g_qh[((bh * 128 + m16) * 4 + kstep) * 32 + lane] =
                    make_uint4(a0, a1, a2, a3);
            }
        }
    } else if (w == 1) {
        // K -> fp16 b-fragment pairs, straight from accumulators.
#pragma unroll
        for (int mt = 0; mt < 4; mt++) {
            int r = m0 + wm * 64 + mt * 16 + gid;
            int t = r >> 6, key8 = (r >> 3) & 7;
            unsigned s_b0r0, s_b1r0, s_b0r8, s_b1r8;
#pragma unroll
            for (int sp = 0; sp < 2; sp++) {
                int ntA = 2 * sp, ntB = ntA + 1;
                int nA = n0 + wn * 32 + ntA * 8 + tig * 2;
                int nB = nA + 8;
                float bA0 = bias[nA], bA1 = bias[nA + 1];
                float bB0 = bias[nB], bB1 = bias[nB + 1];
                unsigned b0r0 = ph(acc[mt][ntA][0] + bA0, acc[mt][ntA][1] + bA1);
                unsigned b1r0 = ph(acc[mt][ntB][0] + bB0, acc[mt][ntB][1] + bB1);
                unsigned b0r8 = ph(acc[mt][ntA][2] + bA0, acc[mt][ntA][3] + bA1);
                unsigned b1r8 = ph(acc[mt][ntB][2] + bB0, acc[mt][ntB][3] + bB1);
                if (sp == 0) { s_b0r0 = b0r0; s_b1r0 = b1r0; s_b0r8 = b0r8; s_b1r8 = b1r8; }
                else {
                    uint4* p = g_kh + bh * 16384;
                    p[(((t * 2 + kp) * 8 + key8) * 8 + gid) * 4 + tig] =
                        make_uint4(s_b0r0, s_b1r0, b0r0, b1r0);
                    p[(((t * 2 + kp) * 8 + key8 + 1) * 8 + gid) * 4 + tig] =
                        make_uint4(s_b0r8, s_b1r8, b0r8, b1r8);
                }
            }
        }
    } else {
        // V -> fp16 b-fragment pairs via per-warp smem transpose (pad 12).
        float* sv = dyn + warp * 200;   // reuses A buffer 0 (mainloop ended on buf 1)
        int tt = blockIdx.x * 2 + wm;
        uint2 vbuf[4];
#pragma unroll
        for (int mt = 0; mt < 4; mt++) {
#pragma unroll
            for (int nt = 0; nt < 4; nt++) {
                int nb = n0 + wn * 32 + nt * 8;
                int nf = nb + tig * 2;
                float c0 = acc[mt][nt][0] + bias[nf];
                float c1 = acc[mt][nt][1] + bias[nf + 1];
                float c2 = acc[mt][nt][2] + bias[nf];
                float c3 = acc[mt][nt][3] + bias[nf + 1];
                sv[gid * 12 + tig * 2]           = c0;
                sv[gid * 12 + tig * 2 + 1]       = c1;
                sv[(gid + 8) * 12 + tig * 2]     = c2;
                sv[(gid + 8) * 12 + tig * 2 + 1] = c3;
                __syncwarp();
                float a0 = sv[(2 * tig) * 12 + gid];
                float a1 = sv[(2 * tig + 1) * 12 + gid];
                float a2 = sv[(2 * tig + 8) * 12 + gid];
                float a3 = sv[(2 * tig + 9) * 12 + gid];
                __syncwarp();
                uint2 val = make_uint2(ph(a0, a1), ph(a2, a3));
                if ((mt & 1) == 0) vbuf[nt] = val;
                else {
                    int jp = mt >> 1;
                    int hv = nb >> 6;
                    int ev3 = (nb & 63) >> 3;
                    size_t bhv = (size_t)b * HH + hv;
                    g_vh[bhv * 16384 + (size_t)tt * 512 + ((jp * 8 + ev3) * 8 + gid) * 4 + tig] =
                        make_uint4(vbuf[nt].x, vbuf[nt].y, val.x, val.y);
                }
            }
        }
    }
}

// ---------------------------------------------------------------------------
// Kernel 2: flash attention, full fp16 tensor path, no online max (Q carries
// the log2-domain scale), row sums via ones-column MMA. Softmax interleaved
// with PV per half-tile (jp): QK -> [softmax(jp) -> PV(jp)] x2, so jp=1's
// MUFU/FMA overlaps jp=0's draining HMMAs in-order.
// ---------------------------------------------------------------------------
#define KU4PT 512                            // uint4 per K tile (8 KB)
#define VU4PT 512                            // uint4 per V tile (8 KB)
#define ATTN_SMEM ((2*KU4PT + 2*VU4PT) * 16) // 32768 B

extern __shared__ float smx[];

__global__ __launch_bounds__(256, 2) void attn_mma(const float* __restrict__ mask)
{
    uint4* Ksm = (uint4*)smx;
    uint4* Vsm = Ksm + 2 * KU4PT;

    int bh = blockIdx.y, b = bh >> 3, h = bh & 7;
    int m0 = blockIdx.x * 128;
    int tid = threadIdx.x, lane = tid & 31, w = tid >> 5;
    int gid = lane >> 2, tig = lane & 3;

    const uint4*  kpf  = g_kh + (size_t)bh * 16384;
    const uint4*  vpf  = g_vh + (size_t)bh * 16384;
    const float*  mrow = mask + (size_t)b * SS;

    auto stageKV = [&](int buf, int t) {
        uint4* Kb = Ksm + buf * KU4PT;
        uint4* Vb = Vsm + buf * VU4PT;
        const uint4* ks = kpf + t * KU4PT;
        const uint4* vs = vpf + t * VU4PT;
#pragma unroll
        for (int i = tid; i < 512; i += 256) cpa16(&Kb[i], &ks[i]);
#pragma unroll
        for (int i = tid; i < 512; i += 256) cpa16(&Vb[i], &vs[i]);
        cp_commit();
    };

    stageKV(0, 0);

    int r0 = w * 16 + gid;
    int m16 = (m0 >> 4) + w;

    // Q fp16 a-fragments -> registers (once; 4 LDG.128)
    uint4 qf4[4];
#pragma unroll
    for (int s = 0; s < 4; s++)
        qf4[s] = g_qh[(((size_t)bh * 128 + m16) * 4 + s) * 32 + lane];

    float lacc[4] = {0.f, 0.f, 0.f, 0.f};
    float oacc[8][4];
#pragma unroll
    for (int nt = 0; nt < 8; nt++)
#pragma unroll
        for (int j = 0; j < 4; j++) oacc[nt][j] = 0.f;

    for (int t = 0; t < 32; t++) {
        int t0 = t * 64;
        cp_wait0();
        __syncthreads();
        if (t < 31) stageKV((t + 1) & 1, t + 1);

        const uint4* Kb = Ksm + (t & 1) * KU4PT;
        const uint4* Vb = Vsm + (t & 1) * VU4PT;

        // ---- S = Qs @ K^T (fp16 m16n8k16; S already in log2 units) ----
        float sacc[8][4];
#pragma unroll
        for (int nt = 0; nt < 8; nt++)
#pragma unroll
            for (int j = 0; j < 4; j++) sacc[nt][j] = 0.f;

#pragma unroll
        for (int kp = 0; kp < 2; kp++) {
            const unsigned* afe = (const unsigned*)&qf4[2 * kp];
            const unsigned* afo = (const unsigned*)&qf4[2 * kp + 1];
#pragma unroll
            for (int nt = 0; nt < 8; nt++) {
                uint4 k4 = Kb[((kp * 8 + nt) * 8 + gid) * 4 + tig];
                mma16h(sacc[nt], afe, k4.x, k4.y);
                mma16h(sacc[nt], afo, k4.z, k4.w);
            }
        }

        // ---- per half-tile: softmax(jp) then PV(jp); jp=1 softmax overlaps
        //      jp=0's draining HMMAs ----
#pragma unroll
        for (int jp = 0; jp < 2; jp++) {
#pragma unroll
            for (int nt = 4 * jp; nt < 4 * jp + 4; nt++) {
                float2 mv = *(const float2*)&mrow[t0 + nt * 8 + tig * 2];
                float ad0 = (1.f - mv.x) * NEG2F, ad1 = (1.f - mv.y) * NEG2F;
                sacc[nt][0] = ex2(sacc[nt][0] * mv.x + ad0);
                sacc[nt][1] = ex2(sacc[nt][1] * mv.y + ad1);
                sacc[nt][2] = ex2(sacc[nt][2] * mv.x + ad0);
                sacc[nt][3] = ex2(sacc[nt][3] * mv.y + ad1);
            }
            unsigned afe[4], afo[4];
            afe[0] = ph(sacc[4*jp][0],   sacc[4*jp][1]);
            afe[1] = ph(sacc[4*jp][2],   sacc[4*jp][3]);
            afe[2] = ph(sacc[4*jp+1][0], sacc[4*jp+1][1]);
            afe[3] = ph(sacc[4*jp+1][2], sacc[4*jp+1][3]);
            afo[0] = ph(sacc[4*jp+2][0], sacc[4*jp+2][1]);
            afo[1] = ph(sacc[4*jp+2][2], sacc[4*jp+2][3]);
            afo[2] = ph(sacc[4*jp+3][0], sacc[4*jp+3][1]);
            afo[3] = ph(sacc[4*jp+3][2], sacc[4*jp+3][3]);
            mma16h(lacc, afe, ONE2H, ONE2H);
            mma16h(lacc, afo, ONE2H, ONE2H);
#pragma unroll
            for (int nt = 0; nt < 8; nt++) {
                uint4 v4 = Vb[((jp * 8 + nt) * 8 + gid) * 4 + tig];
                mma16h(oacc[nt], afe, v4.x, v4.y);
                mma16h(oacc[nt], afo, v4.z, v4.w);
            }
        }
    }

    // lacc[0]/lacc[2] are full row sums (ones-column trick)
    int s0r = m0 + r0, s1r = s0r + 8;
    float q0 = mrow[s0r] / lacc[0];
    float q1 = mrow[s1r] / lacc[2];
#pragma unroll
    for (int ks = 0; ks < 4; ks++) {
        uint4 hv;
        hv.x = ph(oacc[2*ks][0] * q0,   oacc[2*ks][1] * q0);
        hv.y = ph(oacc[2*ks][2] * q1,   oacc[2*ks][3] * q1);
        hv.z = ph(oacc[2*ks+1][0] * q0, oacc[2*ks+1][1] * q0);
        hv.w = ph(oacc[2*ks+1][2] * q1, oacc[2*ks+1][3] * q1);
        g_hh[(((size_t)b * 128 + m16) * 32 + h * 4 + ks) * 32 + lane] = hv;
    }
}

// ---------------------------------------------------------------------------
// Kernel 3: output projection, full fp16 (same pipeline shape as qkv).
// ---------------------------------------------------------------------------
#define PROJ_SMEM 32768

__global__ __launch_bounds__(256, 2) void proj_mma(
    const float* __restrict__ b0, float* __restrict__ out)
{
    extern __shared__ float dyn[];
    uint4* A4 = (uint4*)dyn;          // 2 * 512
    uint4* B4 = A4 + 1024;            // 2 * 512

    int b = blockIdx.z;
    int m0 = blockIdx.x * 128, n0 = blockIdx.y * 128;
    int m16_0 = m0 >> 4, n8_0 = n0 >> 3;
    int tid = threadIdx.x, lane = tid & 31, warp = tid >> 5;
    int wm = warp & 1, wn = warp >> 1;
    int gid = lane >> 2, tig = lane & 3;

    const uint4* ha = g_hh + (size_t)b * 128 * 32 * 32;
    const uint4* wb = g_wbh + (size_t)3 * 16 * 64 * 32;

    auto stage = [&](int buf, int it) {
        uint4* Ab = A4 + buf * 512;
        uint4* Bb = B4 + buf * 512;
#pragma unroll
        for (int i = tid; i < 512; i += 256) {
            int ks = i >> 8, rem = i & 255;
            int m16l = rem >> 5, ln = rem & 31;
            cpa16(&Ab[i], &ha[((size_t)(m16_0 + m16l) * 32 + it * 2 + ks) * 32 + ln]);
        }
#pragma unroll
        for (int i = tid; i < 512; i += 256) {
            int n8l = i >> 5, ln = i & 31;
            cpa16(&Bb[i], &wb[((size_t)it * 64 + n8_0 + n8l) * 32 + ln]);
        }
        cp_commit();
    };

    float acc[4][4][4];
#pragma unroll
    for (int mt = 0; mt < 4; mt++)
#pragma unroll
        for (int nt = 0; nt < 4; nt++)
#pragma unroll
            for (int j = 0; j < 4; j++) acc[mt][nt][j] = 0.f;

    stage(0, 0);
    for (int it = 0; it < 16; it++) {
        cp_wait0();
        __syncthreads();
        if (it < 15) stage((it + 1) & 1, it + 1);
        const uint4* Ab = A4 + (it & 1) * 512;
        const uint4* Bb = B4 + (it & 1) * 512;

        uint4 bf[4];
#pragma unroll
        for (int nt = 0; nt < 4; nt++)
            bf[nt] = Bb[(wn * 4 + nt) * 32 + lane];
#pragma unroll
        for (int kp = 0; kp < 2; kp++) {
            uint4 af[4];
#pragma unroll
            for (int mt = 0; mt < 4; mt++)
                af[mt] = Ab[(kp * 8 + wm * 4 + mt) * 32 + lane];
#pragma unroll
            for (int mt = 0; mt < 4; mt++)
#pragma unroll
                for (int nt = 0; nt < 4; nt++)
                    mma16h(acc[mt][nt], (const unsigned*)&af[mt],
                           kp ? bf[nt].z : bf[nt].x, kp ? bf[nt].w : bf[nt].y);
        }
    }

#pragma unroll
    for (int mt = 0; mt < 4; mt++)
#pragma unroll
        for (int nt = 0; nt < 4; nt++) {
            int n = n0 + wn * 32 + nt * 8 + tig * 2;
            int r = m0 + wm * 64 + mt * 16 + gid;
            float b0v = b0[n], b1v = b0[n + 1];
            size_t c0 = ((size_t)b * DD + n) * SS;
            size_t c1 = c0 + SS;
            out[c0 + r]     = acc[mt][nt][0] + b0v;
            out[c1 + r]     = acc[mt][nt][1] + b1v;
            out[c0 + r + 8] = acc[mt][nt][2] + b0v;
            out[c1 + r + 8] = acc[mt][nt][3] + b1v;
        }
}

// ---------------------------------------------------------------------------
extern "C" void kernel_launch(void* const* d_in, const int* in_sizes, int n_in,
                              void* d_out, int out_size)
{
    const float* x    = (const float*)d_in[0];
    const float* mask = (const float*)d_in[1];
    const float* Wq   = (const float*)d_in[2];
    const float* bq   = (const float*)d_in[3];
    const float* Wk   = (const float*)d_in[4];
    const float* bk   = (const float*)d_in[5];
    const float* Wv   = (const float*)d_in[6];
    const float* bv   = (const float*)d_in[7];
    const float* W0   = (const float*)d_in[8];
    const float* b0   = (const float*)d_in[9];
    float* out = (float*)d_out;

    cudaFuncSetAttribute(qkv_mma,
                         cudaFuncAttributeMaxDynamicSharedMemorySize, QKV_SMEM);
    cudaFuncSetAttribute(attn_mma,
                         cudaFuncAttributeMaxDynamicSharedMemorySize, ATTN_SMEM);
    cudaFuncSetAttribute(proj_mma,
                         cudaFuncAttributeMaxDynamicSharedMemorySize, PROJ_SMEM);

    round_xw<<<1536, 256>>>(x, Wq, Wk, Wv, W0);
    qkv_mma<<<dim3(SS/128, DD/128, BB*3), 256, QKV_SMEM>>>(bq, bk, bv);
    attn_mma<<<dim3(SS/128, BB*HH), 256, ATTN_SMEM>>>(mask);
    proj_mma<<<dim3(SS/128, DD/128, BB), 256, PROJ_SMEM>>>(b0, out);
}